// round 1
// baseline (speedup 1.0000x reference)
#include <cuda_runtime.h>
#include <math.h>

#define S 2048
#define HID 2048
#define HQ 16
#define HKV 2
#define HD 128
#define G_GRP 8          // HQ / HKV
#define CS 128
#define NC 16            // S / CS
#define WIN 16
#define NBLK 8           // BUDGET / CS
#define ALPHA 0.8f
#define MIXL 0.5f
#define SCALE 0.08838834764831845f  // 128^-0.5
#define NEGV -1000000000.0f

// ---------------- scratch (device globals; no allocation allowed) ----------
__device__ float g_q[S * HQ * HD];       // [s][h*128+d]
__device__ float g_k[S * HKV * HD];      // [s][h*128+d]
__device__ float g_v[S * HKV * HD];
__device__ float g_kcmean[HKV * NC * HD];
__device__ float g_kcmax[HKV * NC * HD];
__device__ unsigned g_sel[HKV * S];
__device__ float g_attn[S * HQ * HD];    // [s][h*128+d]

// ---------------- generic tiled SGEMM with optional bias -------------------
#define BM 128
#define BN 128
#define BK 8
#define TM 8
#define TN 8
__global__ __launch_bounds__(256) void sgemm_bias(
    const float* __restrict__ A, const float* __restrict__ B,
    const float* __restrict__ bias, float* __restrict__ C,
    int M, int N, int K)
{
    __shared__ float As[BK][BM];
    __shared__ float Bs[BK][BN];
    int tid = threadIdx.x;
    int bx = blockIdx.x, by = blockIdx.y;
    int tx = (tid % 16) * TN;
    int ty = (tid / 16) * TM;

    float acc[TM][TN];
    #pragma unroll
    for (int i = 0; i < TM; i++)
        #pragma unroll
        for (int j = 0; j < TN; j++) acc[i][j] = 0.f;

    int aRow = tid >> 1;          // 0..127
    int aCol = (tid & 1) * 4;     // 0 or 4
    int bRow = tid >> 5;          // 0..7
    int bCol = (tid & 31) * 4;    // 0..124

    const float* Ab = A + (size_t)by * BM * K;
    const float* Bb = B + (size_t)bx * BN;

    for (int k0 = 0; k0 < K; k0 += BK) {
        float4 a4 = *(const float4*)(Ab + (size_t)aRow * K + k0 + aCol);
        As[aCol + 0][aRow] = a4.x;
        As[aCol + 1][aRow] = a4.y;
        As[aCol + 2][aRow] = a4.z;
        As[aCol + 3][aRow] = a4.w;
        float4 b4 = *(const float4*)(Bb + (size_t)(k0 + bRow) * N + bCol);
        *(float4*)&Bs[bRow][bCol] = b4;
        __syncthreads();
        #pragma unroll
        for (int kk = 0; kk < BK; kk++) {
            float ar[TM], br[TN];
            #pragma unroll
            for (int i = 0; i < TM; i++) ar[i] = As[kk][ty + i];
            #pragma unroll
            for (int j = 0; j < TN; j++) br[j] = Bs[kk][tx + j];
            #pragma unroll
            for (int i = 0; i < TM; i++)
                #pragma unroll
                for (int j = 0; j < TN; j++) acc[i][j] += ar[i] * br[j];
        }
        __syncthreads();
    }

    #pragma unroll
    for (int i = 0; i < TM; i++) {
        int row = by * BM + ty + i;
        #pragma unroll
        for (int j = 0; j < TN; j += 4) {
            int col = bx * BN + tx + j;
            float b0 = 0.f, b1 = 0.f, b2 = 0.f, b3 = 0.f;
            if (bias) { b0 = bias[col]; b1 = bias[col+1]; b2 = bias[col+2]; b3 = bias[col+3]; }
            float4 o;
            o.x = acc[i][j+0] + b0;
            o.y = acc[i][j+1] + b1;
            o.z = acc[i][j+2] + b2;
            o.w = acc[i][j+3] + b3;
            *(float4*)(C + (size_t)row * N + col) = o;
        }
    }
}

// ---------------- RoPE -----------------------------------------------------
__global__ void rope_kernel(float* __restrict__ x, const float* __restrict__ cosb,
                            const float* __restrict__ sinb, int H, int stride)
{
    int idx = blockIdx.x * blockDim.x + threadIdx.x;  // S*H*64 total
    if (idx >= S * H * 64) return;
    int d = idx & 63;
    int h = (idx >> 6) % H;
    int s = idx / (64 * H);
    float c0 = cosb[s * HD + d],      s0 = sinb[s * HD + d];
    float c1 = cosb[s * HD + d + 64], s1 = sinb[s * HD + d + 64];
    float* p = x + (size_t)s * stride + h * HD;
    float x0 = p[d], x1 = p[d + 64];
    p[d]      = x0 * c0 - x1 * s0;   // x*cos + (-x[d+64])*sin
    p[d + 64] = x1 * c1 + x0 * s1;   // x*cos + ( x[d-64])*sin
}

// ---------------- per-chunk K stats ----------------------------------------
__global__ void blockstats_kernel()
{
    int c = blockIdx.x & 15;
    int h = blockIdx.x >> 4;
    int d = threadIdx.x;  // 128
    float sum = 0.f, mx = -INFINITY;
    for (int r = 0; r < CS; r++) {
        float v = g_k[(size_t)(c * CS + r) * (HKV * HD) + h * HD + d];
        sum += v;
        mx = fmaxf(mx, v);
    }
    g_kcmean[(h * NC + c) * HD + d] = sum * (1.f / CS);
    g_kcmax [(h * NC + c) * HD + d] = mx;
}

__device__ __forceinline__ float warpsum(float v)
{
    #pragma unroll
    for (int o = 16; o; o >>= 1) v += __shfl_xor_sync(0xffffffffu, v, o);
    return v;
}

// ---------------- block scores + top-8 selection (warp per (h,q)) ----------
__global__ __launch_bounds__(256) void score_kernel()
{
    int w = blockIdx.x * 8 + (threadIdx.x >> 5);   // HKV*S warps
    int lane = threadIdx.x & 31;
    int h = w >> 11;        // /2048
    int q = w & 2047;

    float qv[G_GRP][4];
    #pragma unroll
    for (int g = 0; g < G_GRP; g++)
        #pragma unroll
        for (int j = 0; j < 4; j++)
            qv[g][j] = g_q[(size_t)q * (HQ * HD) + (h * G_GRP + g) * HD + lane + 32 * j];

    int qblk = q >> 7;
    float score[NC];
    for (int c = 0; c < NC; c++) {
        if (c > qblk) { score[c] = NEGV; continue; }
        float pm[G_GRP], px[G_GRP];
        #pragma unroll
        for (int g = 0; g < G_GRP; g++) { pm[g] = 0.f; px[g] = 0.f; }
        #pragma unroll
        for (int j = 0; j < 4; j++) {
            float km = g_kcmean[(h * NC + c) * HD + lane + 32 * j];
            float kx = g_kcmax [(h * NC + c) * HD + lane + 32 * j];
            #pragma unroll
            for (int g = 0; g < G_GRP; g++) { pm[g] += qv[g][j] * km; px[g] += qv[g][j] * kx; }
        }
        float meanv = 0.f, maxv = -INFINITY;
        #pragma unroll
        for (int g = 0; g < G_GRP; g++) {
            float a = warpsum(pm[g]);
            float b = warpsum(px[g]);
            float sg = SCALE * (MIXL * a + (1.f - MIXL) * b);
            meanv += sg;
            maxv = fmaxf(maxv, sg);
        }
        score[c] = ALPHA * (meanv * (1.f / G_GRP)) + (1.f - ALPHA) * maxv;
    }

    unsigned sel = 0;
    int nsel = min(NBLK, qblk + 1);
    for (int it = 0; it < nsel; it++) {
        float best = -INFINITY; int bi = 0;
        for (int c = 0; c <= qblk; c++)
            if (!((sel >> c) & 1) && score[c] > best) { best = score[c]; bi = c; }
        sel |= 1u << bi;
    }
    if (lane == 0) g_sel[h * S + q] = sel;
}

// ---------------- block-sparse attention (warp per (h,q)) ------------------
__global__ __launch_bounds__(256) void attn_kernel(const int* __restrict__ am)
{
    int w = blockIdx.x * 8 + (threadIdx.x >> 5);   // HQ*S warps
    int lane = threadIdx.x & 31;
    int h = w >> 11;
    int q = w & 2047;
    int kvh = h >> 3;

    float qv[4];
    #pragma unroll
    for (int j = 0; j < 4; j++)
        qv[j] = g_q[(size_t)q * (HQ * HD) + h * HD + lane + 32 * j];

    unsigned sel = g_sel[kvh * S + q];
    float m = -INFINITY, l = 0.f;
    float acc[4] = {0.f, 0.f, 0.f, 0.f};
    int qblk = q >> 7;

    for (int c = 0; c <= qblk; c++) {
        int lo = c << 7;
        int hi = min(lo + CS - 1, q);
        if (!((sel >> c) & 1)) lo = max(lo, q - (WIN - 1));
        for (int kp = lo; kp <= hi; kp++) {
            if (am[kp] <= 0) continue;
            const float* kr = g_k + (size_t)kp * (HKV * HD) + kvh * HD;
            float part = qv[0] * kr[lane] + qv[1] * kr[lane + 32]
                       + qv[2] * kr[lane + 64] + qv[3] * kr[lane + 96];
            #pragma unroll
            for (int o = 16; o; o >>= 1) part += __shfl_xor_sync(0xffffffffu, part, o);
            float logit = part * SCALE;
            float p;
            if (logit > m) {
                float r = __expf(m - logit);
                l *= r;
                acc[0] *= r; acc[1] *= r; acc[2] *= r; acc[3] *= r;
                m = logit;
                p = 1.f;
            } else {
                p = __expf(logit - m);
            }
            l += p;
            const float* vr = g_v + (size_t)kp * (HKV * HD) + kvh * HD;
            acc[0] += p * vr[lane];
            acc[1] += p * vr[lane + 32];
            acc[2] += p * vr[lane + 64];
            acc[3] += p * vr[lane + 96];
        }
    }
    float inv = 1.f / l;
    #pragma unroll
    for (int j = 0; j < 4; j++)
        g_attn[(size_t)q * (HQ * HD) + h * HD + lane + 32 * j] = acc[j] * inv;
}

// ---------------- launch ----------------------------------------------------
extern "C" void kernel_launch(void* const* d_in, const int* in_sizes, int n_in,
                              void* d_out, int out_size)
{
    const float* hs   = (const float*)d_in[0];
    const float* cosb = (const float*)d_in[1];
    const float* sinb = (const float*)d_in[2];
    const int*   am   = (const int*)d_in[3];
    // d_in[4] = input_length (unused; S fixed)
    const float* Wq = (const float*)d_in[5];
    const float* bq = (const float*)d_in[6];
    const float* Wk = (const float*)d_in[7];
    const float* bk = (const float*)d_in[8];
    const float* Wv = (const float*)d_in[9];
    const float* bv = (const float*)d_in[10];
    const float* Wo = (const float*)d_in[11];
    float* out = (float*)d_out;

    float *pq, *pk, *pv, *pattn;
    cudaGetSymbolAddress((void**)&pq, g_q);
    cudaGetSymbolAddress((void**)&pk, g_k);
    cudaGetSymbolAddress((void**)&pv, g_v);
    cudaGetSymbolAddress((void**)&pattn, g_attn);

    // projections
    sgemm_bias<<<dim3(HQ * HD / BN, S / BM), 256>>>(hs, Wq, bq, pq, S, HQ * HD, HID);
    sgemm_bias<<<dim3(HKV * HD / BN, S / BM), 256>>>(hs, Wk, bk, pk, S, HKV * HD, HID);
    sgemm_bias<<<dim3(HKV * HD / BN, S / BM), 256>>>(hs, Wv, bv, pv, S, HKV * HD, HID);

    // rope
    rope_kernel<<<(S * HQ * 64 + 255) / 256, 256>>>(pq, cosb, sinb, HQ, HQ * HD);
    rope_kernel<<<(S * HKV * 64 + 255) / 256, 256>>>(pk, cosb, sinb, HKV, HKV * HD);

    // chunk stats + selection
    blockstats_kernel<<<HKV * NC, HD>>>();
    score_kernel<<<HKV * S / 8, 256>>>();

    // sparse attention
    attn_kernel<<<HQ * S / 8, 256>>>(am);

    // output projection (no bias)
    sgemm_bias<<<dim3(HID / BN, S / BM), 256>>>(pattn, Wo, nullptr, out, S, HID, HQ * HD);
}

// round 4
// speedup vs baseline: 1.1068x; 1.1068x over previous
#include <cuda_runtime.h>
#include <math.h>
#include <stdint.h>

#define S 2048
#define HID 2048
#define HQ 16
#define HKV 2
#define HD 128
#define G_GRP 8          // HQ / HKV
#define CS 128
#define NC 16            // S / CS
#define WIN 16
#define NBLK 8           // BUDGET / CS
#define ALPHA 0.8f
#define MIXL 0.5f
#define SCALE 0.08838834764831845f  // 128^-0.5
#define NEGV -1000000000.0f

// ---------------- scratch (device globals; no allocation allowed) ----------
__device__ float g_q[S * HQ * HD];       // [s][h*128+d]
__device__ float g_k[S * HKV * HD];      // [s][h*128+d]
__device__ float g_v[S * HKV * HD];
__device__ float g_kcmean[HKV * NC * HD];
__device__ float g_kcmax[HKV * NC * HD];
__device__ unsigned g_sel[HKV * S];
__device__ float g_attn[S * HQ * HD];    // [s][h*128+d]

// ---------------- 3xTF32 tensor-core GEMM ----------------------------------
// C[M,N] = A[M,K] @ B[K,N] (+bias). fp32 in/out; each operand split into
// hi = tf32(x), lo = tf32(x - hi); C ~= Ah*Bh + Ah*Bl + Al*Bh  (~fp32 accuracy).
// Block tile 128x128x16, 8 warps of 32x64 each.
#define GBM 128
#define GBN 128
#define GBK 16
#define ASTR 132   // padded m-stride for As[k][m]
#define BSTR 132   // padded n-stride for Bs[k][n]

__device__ __forceinline__ uint32_t f2tf32(float f)
{
    uint32_t r;
    asm("cvt.rna.tf32.f32 %0, %1;" : "=r"(r) : "f"(f));
    return r;
}

__device__ __forceinline__ void split_tf32(float x, uint32_t& h, uint32_t& l)
{
    h = f2tf32(x);
    l = f2tf32(x - __uint_as_float(h));
}

__device__ __forceinline__ void mma_tf32(float c[4], const uint32_t a[4], const uint32_t b[2])
{
    asm volatile(
        "mma.sync.aligned.m16n8k8.row.col.f32.tf32.tf32.f32 "
        "{%0,%1,%2,%3}, {%4,%5,%6,%7}, {%8,%9}, {%0,%1,%2,%3};"
        : "+f"(c[0]), "+f"(c[1]), "+f"(c[2]), "+f"(c[3])
        : "r"(a[0]), "r"(a[1]), "r"(a[2]), "r"(a[3]), "r"(b[0]), "r"(b[1]));
}

__global__ __launch_bounds__(256) void gemm_3xtf32(
    const float* __restrict__ A, const float* __restrict__ B,
    const float* __restrict__ bias, float* __restrict__ C,
    int M, int N, int K)
{
    __shared__ uint32_t AsH[GBK][ASTR];
    __shared__ uint32_t AsL[GBK][ASTR];
    __shared__ uint32_t BsH[GBK][BSTR];
    __shared__ uint32_t BsL[GBK][BSTR];

    int tid = threadIdx.x;
    int lane = tid & 31;
    int wid = tid >> 5;
    int wm = (wid & 3) * 32;       // warp M offset within block tile
    int wn = (wid >> 2) * 64;      // warp N offset

    const float* Ab = A + (size_t)blockIdx.y * GBM * K;
    const float* Bb = B + (size_t)blockIdx.x * GBN;

    // global load assignment
    int ar = tid >> 2;             // 0..63 (rows ar, ar+64)
    int ak = (tid & 3) * 4;        // k 0,4,8,12
    int bkr = tid >> 5;            // 0..7 (k rows bkr, bkr+8)
    int bn = (tid & 31) * 4;       // n 0..124

    float4 ra0, ra1, rb0, rb1;
    ra0 = *(const float4*)(Ab + (size_t)ar * K + ak);
    ra1 = *(const float4*)(Ab + (size_t)(ar + 64) * K + ak);
    rb0 = *(const float4*)(Bb + (size_t)bkr * N + bn);
    rb1 = *(const float4*)(Bb + (size_t)(bkr + 8) * N + bn);

    float acc[2][8][4];
    #pragma unroll
    for (int mt = 0; mt < 2; mt++)
        #pragma unroll
        for (int nt = 0; nt < 8; nt++)
            #pragma unroll
            for (int c = 0; c < 4; c++) acc[mt][nt][c] = 0.f;

    int qrow = lane >> 2;   // 0..7
    int qcol = lane & 3;    // 0..3

    for (int k0 = 0; k0 < K; k0 += GBK) {
        // stage current tile to smem, hi/lo split
        {
            uint32_t h, l;
            split_tf32(ra0.x, h, l); AsH[ak + 0][ar] = h; AsL[ak + 0][ar] = l;
            split_tf32(ra0.y, h, l); AsH[ak + 1][ar] = h; AsL[ak + 1][ar] = l;
            split_tf32(ra0.z, h, l); AsH[ak + 2][ar] = h; AsL[ak + 2][ar] = l;
            split_tf32(ra0.w, h, l); AsH[ak + 3][ar] = h; AsL[ak + 3][ar] = l;
            split_tf32(ra1.x, h, l); AsH[ak + 0][ar + 64] = h; AsL[ak + 0][ar + 64] = l;
            split_tf32(ra1.y, h, l); AsH[ak + 1][ar + 64] = h; AsL[ak + 1][ar + 64] = l;
            split_tf32(ra1.z, h, l); AsH[ak + 2][ar + 64] = h; AsL[ak + 2][ar + 64] = l;
            split_tf32(ra1.w, h, l); AsH[ak + 3][ar + 64] = h; AsL[ak + 3][ar + 64] = l;
            split_tf32(rb0.x, h, l); BsH[bkr][bn + 0] = h; BsL[bkr][bn + 0] = l;
            split_tf32(rb0.y, h, l); BsH[bkr][bn + 1] = h; BsL[bkr][bn + 1] = l;
            split_tf32(rb0.z, h, l); BsH[bkr][bn + 2] = h; BsL[bkr][bn + 2] = l;
            split_tf32(rb0.w, h, l); BsH[bkr][bn + 3] = h; BsL[bkr][bn + 3] = l;
            split_tf32(rb1.x, h, l); BsH[bkr + 8][bn + 0] = h; BsL[bkr + 8][bn + 0] = l;
            split_tf32(rb1.y, h, l); BsH[bkr + 8][bn + 1] = h; BsL[bkr + 8][bn + 1] = l;
            split_tf32(rb1.z, h, l); BsH[bkr + 8][bn + 2] = h; BsL[bkr + 8][bn + 2] = l;
            split_tf32(rb1.w, h, l); BsH[bkr + 8][bn + 3] = h; BsL[bkr + 8][bn + 3] = l;
        }
        __syncthreads();

        if (k0 + GBK < K) {
            ra0 = *(const float4*)(Ab + (size_t)ar * K + (k0 + GBK) + ak);
            ra1 = *(const float4*)(Ab + (size_t)(ar + 64) * K + (k0 + GBK) + ak);
            rb0 = *(const float4*)(Bb + (size_t)(k0 + GBK + bkr) * N + bn);
            rb1 = *(const float4*)(Bb + (size_t)(k0 + GBK + bkr + 8) * N + bn);
        }

        #pragma unroll
        for (int ks = 0; ks < 2; ks++) {
            int kb = ks * 8;
            uint32_t afH[2][4], afL[2][4];
            #pragma unroll
            for (int mt = 0; mt < 2; mt++) {
                int mb = wm + mt * 16;
                afH[mt][0] = AsH[kb + qcol][mb + qrow];
                afH[mt][1] = AsH[kb + qcol][mb + qrow + 8];
                afH[mt][2] = AsH[kb + qcol + 4][mb + qrow];
                afH[mt][3] = AsH[kb + qcol + 4][mb + qrow + 8];
                afL[mt][0] = AsL[kb + qcol][mb + qrow];
                afL[mt][1] = AsL[kb + qcol][mb + qrow + 8];
                afL[mt][2] = AsL[kb + qcol + 4][mb + qrow];
                afL[mt][3] = AsL[kb + qcol + 4][mb + qrow + 8];
            }
            uint32_t bfH[8][2], bfL[8][2];
            #pragma unroll
            for (int nt = 0; nt < 8; nt++) {
                int nb = wn + nt * 8;
                bfH[nt][0] = BsH[kb + qcol][nb + qrow];
                bfH[nt][1] = BsH[kb + qcol + 4][nb + qrow];
                bfL[nt][0] = BsL[kb + qcol][nb + qrow];
                bfL[nt][1] = BsL[kb + qcol + 4][nb + qrow];
            }
            #pragma unroll
            for (int mt = 0; mt < 2; mt++)
                #pragma unroll
                for (int nt = 0; nt < 8; nt++) {
                    mma_tf32(acc[mt][nt], afL[mt], bfH[nt]);
                    mma_tf32(acc[mt][nt], afH[mt], bfL[nt]);
                    mma_tf32(acc[mt][nt], afH[mt], bfH[nt]);
                }
        }
        __syncthreads();
    }

    // epilogue
    #pragma unroll
    for (int mt = 0; mt < 2; mt++) {
        int row0 = blockIdx.y * GBM + wm + mt * 16 + qrow;
        #pragma unroll
        for (int nt = 0; nt < 8; nt++) {
            int col = blockIdx.x * GBN + wn + nt * 8 + qcol * 2;
            float b0 = 0.f, b1 = 0.f;
            if (bias) { b0 = bias[col]; b1 = bias[col + 1]; }
            float2 o0 = make_float2(acc[mt][nt][0] + b0, acc[mt][nt][1] + b1);
            float2 o1 = make_float2(acc[mt][nt][2] + b0, acc[mt][nt][3] + b1);
            *(float2*)(C + (size_t)row0 * N + col) = o0;
            *(float2*)(C + (size_t)(row0 + 8) * N + col) = o1;
        }
    }
}

// ---------------- RoPE -----------------------------------------------------
__global__ void rope_kernel(float* __restrict__ x, const float* __restrict__ cosb,
                            const float* __restrict__ sinb, int H, int stride)
{
    int idx = blockIdx.x * blockDim.x + threadIdx.x;  // S*H*64 total
    if (idx >= S * H * 64) return;
    int d = idx & 63;
    int h = (idx >> 6) % H;
    int s = idx / (64 * H);
    float c0 = cosb[s * HD + d],      s0 = sinb[s * HD + d];
    float c1 = cosb[s * HD + d + 64], s1 = sinb[s * HD + d + 64];
    float* p = x + (size_t)s * stride + h * HD;
    float x0 = p[d], x1 = p[d + 64];
    p[d]      = x0 * c0 - x1 * s0;
    p[d + 64] = x1 * c1 + x0 * s1;
}

// ---------------- per-chunk K stats ----------------------------------------
__global__ void blockstats_kernel()
{
    int c = blockIdx.x & 15;
    int h = blockIdx.x >> 4;
    int d = threadIdx.x;  // 128
    float sum = 0.f, mx = -INFINITY;
    for (int r = 0; r < CS; r++) {
        float v = g_k[(size_t)(c * CS + r) * (HKV * HD) + h * HD + d];
        sum += v;
        mx = fmaxf(mx, v);
    }
    g_kcmean[(h * NC + c) * HD + d] = sum * (1.f / CS);
    g_kcmax [(h * NC + c) * HD + d] = mx;
}

__device__ __forceinline__ float warpsum(float v)
{
    #pragma unroll
    for (int o = 16; o; o >>= 1) v += __shfl_xor_sync(0xffffffffu, v, o);
    return v;
}

// ---------------- block scores + top-8 selection (warp per (h,q)) ----------
__global__ __launch_bounds__(256) void score_kernel()
{
    int w = blockIdx.x * 8 + (threadIdx.x >> 5);   // HKV*S warps
    int lane = threadIdx.x & 31;
    int h = w >> 11;
    int q = w & 2047;

    float qv[G_GRP][4];
    #pragma unroll
    for (int g = 0; g < G_GRP; g++)
        #pragma unroll
        for (int j = 0; j < 4; j++)
            qv[g][j] = g_q[(size_t)q * (HQ * HD) + (h * G_GRP + g) * HD + lane + 32 * j];

    int qblk = q >> 7;
    float score[NC];
    for (int c = 0; c < NC; c++) {
        if (c > qblk) { score[c] = NEGV; continue; }
        float pm[G_GRP], px[G_GRP];
        #pragma unroll
        for (int g = 0; g < G_GRP; g++) { pm[g] = 0.f; px[g] = 0.f; }
        #pragma unroll
        for (int j = 0; j < 4; j++) {
            float km = g_kcmean[(h * NC + c) * HD + lane + 32 * j];
            float kx = g_kcmax [(h * NC + c) * HD + lane + 32 * j];
            #pragma unroll
            for (int g = 0; g < G_GRP; g++) { pm[g] += qv[g][j] * km; px[g] += qv[g][j] * kx; }
        }
        float meanv = 0.f, maxv = -INFINITY;
        #pragma unroll
        for (int g = 0; g < G_GRP; g++) {
            float a = warpsum(pm[g]);
            float b = warpsum(px[g]);
            float sg = SCALE * (MIXL * a + (1.f - MIXL) * b);
            meanv += sg;
            maxv = fmaxf(maxv, sg);
        }
        score[c] = ALPHA * (meanv * (1.f / G_GRP)) + (1.f - ALPHA) * maxv;
    }

    unsigned sel = 0;
    int nsel = min(NBLK, qblk + 1);
    for (int it = 0; it < nsel; it++) {
        float best = -INFINITY; int bi = 0;
        for (int c = 0; c <= qblk; c++)
            if (!((sel >> c) & 1) && score[c] > best) { best = score[c]; bi = c; }
        sel |= 1u << bi;
    }
    if (lane == 0) g_sel[h * S + q] = sel;
}

// ---------------- block-sparse attention (warp per (h,q)) ------------------
__global__ __launch_bounds__(256) void attn_kernel(const int* __restrict__ am)
{
    int w = blockIdx.x * 8 + (threadIdx.x >> 5);   // HQ*S warps
    int lane = threadIdx.x & 31;
    int h = w >> 11;
    int q = w & 2047;
    int kvh = h >> 3;

    float qv[4];
    #pragma unroll
    for (int j = 0; j < 4; j++)
        qv[j] = g_q[(size_t)q * (HQ * HD) + h * HD + lane + 32 * j];

    unsigned sel = g_sel[kvh * S + q];
    float m = -INFINITY, l = 0.f;
    float acc[4] = {0.f, 0.f, 0.f, 0.f};
    int qblk = q >> 7;

    for (int c = 0; c <= qblk; c++) {
        int lo = c << 7;
        int hi = min(lo + CS - 1, q);
        if (!((sel >> c) & 1)) lo = max(lo, q - (WIN - 1));
        for (int kp = lo; kp <= hi; kp++) {
            if (am[kp] <= 0) continue;
            const float* kr = g_k + (size_t)kp * (HKV * HD) + kvh * HD;
            float part = qv[0] * kr[lane] + qv[1] * kr[lane + 32]
                       + qv[2] * kr[lane + 64] + qv[3] * kr[lane + 96];
            #pragma unroll
            for (int o = 16; o; o >>= 1) part += __shfl_xor_sync(0xffffffffu, part, o);
            float logit = part * SCALE;
            float p;
            if (logit > m) {
                float r = __expf(m - logit);
                l *= r;
                acc[0] *= r; acc[1] *= r; acc[2] *= r; acc[3] *= r;
                m = logit;
                p = 1.f;
            } else {
                p = __expf(logit - m);
            }
            l += p;
            const float* vr = g_v + (size_t)kp * (HKV * HD) + kvh * HD;
            acc[0] += p * vr[lane];
            acc[1] += p * vr[lane + 32];
            acc[2] += p * vr[lane + 64];
            acc[3] += p * vr[lane + 96];
        }
    }
    float inv = 1.f / l;
    #pragma unroll
    for (int j = 0; j < 4; j++)
        g_attn[(size_t)q * (HQ * HD) + h * HD + lane + 32 * j] = acc[j] * inv;
}

// ---------------- launch ----------------------------------------------------
extern "C" void kernel_launch(void* const* d_in, const int* in_sizes, int n_in,
                              void* d_out, int out_size)
{
    const float* hs   = (const float*)d_in[0];
    const float* cosb = (const float*)d_in[1];
    const float* sinb = (const float*)d_in[2];
    const int*   am   = (const int*)d_in[3];
    // d_in[4] = input_length (unused; S fixed)
    const float* Wq = (const float*)d_in[5];
    const float* bq = (const float*)d_in[6];
    const float* Wk = (const float*)d_in[7];
    const float* bk = (const float*)d_in[8];
    const float* Wv = (const float*)d_in[9];
    const float* bv = (const float*)d_in[10];
    const float* Wo = (const float*)d_in[11];
    float* out = (float*)d_out;

    float *pq, *pk, *pv, *pattn;
    cudaGetSymbolAddress((void**)&pq, g_q);
    cudaGetSymbolAddress((void**)&pk, g_k);
    cudaGetSymbolAddress((void**)&pv, g_v);
    cudaGetSymbolAddress((void**)&pattn, g_attn);

    // projections (3xTF32 tensor cores, ~fp32 accuracy)
    gemm_3xtf32<<<dim3(HQ * HD / GBN, S / GBM), 256>>>(hs, Wq, bq, pq, S, HQ * HD, HID);
    gemm_3xtf32<<<dim3(HKV * HD / GBN, S / GBM), 256>>>(hs, Wk, bk, pk, S, HKV * HD, HID);
    gemm_3xtf32<<<dim3(HKV * HD / GBN, S / GBM), 256>>>(hs, Wv, bv, pv, S, HKV * HD, HID);

    // rope
    rope_kernel<<<(S * HQ * 64 + 255) / 256, 256>>>(pq, cosb, sinb, HQ, HQ * HD);
    rope_kernel<<<(S * HKV * 64 + 255) / 256, 256>>>(pk, cosb, sinb, HKV, HKV * HD);

    // chunk stats + selection
    blockstats_kernel<<<HKV * NC, HD>>>();
    score_kernel<<<HKV * S / 8, 256>>>();

    // sparse attention
    attn_kernel<<<HQ * S / 8, 256>>>(am);

    // output projection (no bias)
    gemm_3xtf32<<<dim3(HID / GBN, S / GBM), 256>>>(pattn, Wo, nullptr, out, S, HID, HQ * HD);
}